// round 2
// baseline (speedup 1.0000x reference)
#include <cuda_runtime.h>
#include <cuda_bf16.h>
#include <cstdint>
#include <cstdio>

#define NN 100000
#define EE 3200000
#define RR 20
#define DD 64

// ---------------- scratch (static device globals; no allocations) ----------------
__device__ float g_t[(size_t)RR * NN * DD];   // 512 MB: t[r][n][d]
__device__ float g_h1[(size_t)NN * DD];       // 25.6 MB: layer-1 output (post-relu)
__device__ int   g_cnt[NN];
__device__ int   g_cursor[NN];
__device__ int   g_rowoff[NN + 1];
__device__ int   g_sorted[EE];                // packed: src | (etype<<20)
__device__ float g_gsum[DD];

// ---------------- prep kernels ----------------
__global__ void zero_kernel() {
    int i = blockIdx.x * blockDim.x + threadIdx.x;
    int stride = gridDim.x * blockDim.x;
    for (; i < NN; i += stride) g_cnt[i] = 0;
    if (blockIdx.x == 0 && threadIdx.x < DD) g_gsum[threadIdx.x] = 0.0f;
}

__global__ void count_kernel(const int* __restrict__ dst) {
    int i = blockIdx.x * blockDim.x + threadIdx.x;
    int stride = gridDim.x * blockDim.x;
    for (; i < EE; i += stride) atomicAdd(&g_cnt[dst[i]], 1);
}

// single-block exclusive scan over g_cnt -> g_rowoff (N=100000)
__global__ void scan_kernel() {
    __shared__ int wsum[32];
    __shared__ int s_carry;
    const int tid = threadIdx.x;
    const int lane = tid & 31;
    const int wid = tid >> 5;
    if (tid == 0) s_carry = 0;
    __syncthreads();
    for (int base = 0; base < NN; base += 1024) {
        int i = base + tid;
        int v = (i < NN) ? g_cnt[i] : 0;
        int x = v;
        #pragma unroll
        for (int off = 1; off < 32; off <<= 1) {
            int y = __shfl_up_sync(0xFFFFFFFFu, x, off);
            if (lane >= off) x += y;
        }
        if (lane == 31) wsum[wid] = x;
        __syncthreads();
        if (wid == 0) {
            int w = wsum[lane];
            #pragma unroll
            for (int off = 1; off < 32; off <<= 1) {
                int y = __shfl_up_sync(0xFFFFFFFFu, w, off);
                if (lane >= off) w += y;
            }
            wsum[lane] = w;
        }
        __syncthreads();
        int carry = s_carry;
        int woff = (wid == 0) ? 0 : wsum[wid - 1];
        if (i < NN) g_rowoff[i] = carry + woff + x - v;   // exclusive
        __syncthreads();
        if (tid == 1023) s_carry = carry + wsum[31];
        __syncthreads();
    }
    if (tid == 0) g_rowoff[NN] = s_carry;
}

__global__ void init_cursor_kernel() {
    int i = blockIdx.x * blockDim.x + threadIdx.x;
    int stride = gridDim.x * blockDim.x;
    for (; i < NN; i += stride) g_cursor[i] = g_rowoff[i];
}

__global__ void scatter_kernel(const int* __restrict__ src,
                               const int* __restrict__ dst,
                               const int* __restrict__ et) {
    int i = blockIdx.x * blockDim.x + threadIdx.x;
    int stride = gridDim.x * blockDim.x;
    for (; i < EE; i += stride) {
        int d = dst[i];
        int pos = atomicAdd(&g_cursor[d], 1);
        g_sorted[pos] = src[i] | (et[i] << 20);
    }
}

// ---------------- GEMM: t[r] = in @ W[r], fp32 with packed f32x2 FMA ----------------
// block tile: 64 rows x 64 cols, 128 threads, each thread 4x8 micro-tile
__global__ __launch_bounds__(128) void gemm_kernel(const float* __restrict__ in,
                                                   const float* __restrict__ W) {
    __shared__ __align__(16) float hs[64 * 68];  // [k][row], stride 68
    __shared__ __align__(16) float ws[64 * 64];  // [k][o]
    const int r = blockIdx.y;
    const int row0 = blockIdx.x * 64;
    const int tid = threadIdx.x;

    // load W[r]: 4096 floats, vector copy
    {
        const float4* wsrc = (const float4*)(W + (size_t)r * 64 * 64);
        float4* wdst = (float4*)ws;
        #pragma unroll
        for (int i = 0; i < 8; i++) wdst[tid + i * 128] = wsrc[tid + i * 128];
    }
    // load h tile transposed into hs[k][row]
    #pragma unroll
    for (int i = 0; i < 8; i++) {
        int idx = tid + i * 128;          // 0..1023
        int row = idx >> 4;               // 0..63
        int k0  = (idx & 15) << 2;        // 0,4,...,60
        int grow = row0 + row;
        float4 v = make_float4(0.f, 0.f, 0.f, 0.f);
        if (grow < NN) v = *(const float4*)(in + (size_t)grow * 64 + k0);
        hs[(k0 + 0) * 68 + row] = v.x;
        hs[(k0 + 1) * 68 + row] = v.y;
        hs[(k0 + 2) * 68 + row] = v.z;
        hs[(k0 + 3) * 68 + row] = v.w;
    }
    __syncthreads();

    const int ty = tid >> 3;   // 0..15 -> rows ty*4
    const int tx = tid & 7;    // 0..7  -> cols tx*8
    unsigned long long acc[4][4];
    #pragma unroll
    for (int i = 0; i < 4; i++)
        #pragma unroll
        for (int j = 0; j < 4; j++) acc[i][j] = 0ull;

    #pragma unroll
    for (int k = 0; k < 64; k++) {
        float4 a4 = *(const float4*)&hs[k * 68 + ty * 4];
        ulonglong2 B0 = *(const ulonglong2*)&ws[k * 64 + tx * 8];
        ulonglong2 B1 = *(const ulonglong2*)&ws[k * 64 + tx * 8 + 4];
        unsigned long long aa0, aa1, aa2, aa3;
        asm("mov.b64 %0, {%1,%1};" : "=l"(aa0) : "r"(__float_as_uint(a4.x)));
        asm("mov.b64 %0, {%1,%1};" : "=l"(aa1) : "r"(__float_as_uint(a4.y)));
        asm("mov.b64 %0, {%1,%1};" : "=l"(aa2) : "r"(__float_as_uint(a4.z)));
        asm("mov.b64 %0, {%1,%1};" : "=l"(aa3) : "r"(__float_as_uint(a4.w)));
        unsigned long long aav[4] = {aa0, aa1, aa2, aa3};
        #pragma unroll
        for (int i = 0; i < 4; i++) {
            asm("fma.rn.f32x2 %0, %1, %2, %0;" : "+l"(acc[i][0]) : "l"(aav[i]), "l"(B0.x));
            asm("fma.rn.f32x2 %0, %1, %2, %0;" : "+l"(acc[i][1]) : "l"(aav[i]), "l"(B0.y));
            asm("fma.rn.f32x2 %0, %1, %2, %0;" : "+l"(acc[i][2]) : "l"(aav[i]), "l"(B1.x));
            asm("fma.rn.f32x2 %0, %1, %2, %0;" : "+l"(acc[i][3]) : "l"(aav[i]), "l"(B1.y));
        }
    }

    #pragma unroll
    for (int i = 0; i < 4; i++) {
        int grow = row0 + ty * 4 + i;
        if (grow < NN) {
            float* dstp = g_t + ((size_t)r * NN + grow) * 64 + tx * 8;
            *(ulonglong2*)dstp       = make_ulonglong2(acc[i][0], acc[i][1]);
            *((ulonglong2*)dstp + 1) = make_ulonglong2(acc[i][2], acc[i][3]);
        }
    }
}

// ---------------- aggregation: one warp per destination node, no atomics ----------------
__global__ __launch_bounds__(256) void agg_kernel(float* __restrict__ out, int relu) {
    int warp = (blockIdx.x * blockDim.x + threadIdx.x) >> 5;
    int lane = threadIdx.x & 31;
    if (warp >= NN) return;
    int s = g_rowoff[warp];
    int e = g_rowoff[warp + 1];
    float2 acc = make_float2(0.f, 0.f);
    #pragma unroll 4
    for (int i = s; i < e; i++) {
        int p = g_sorted[i];
        int src = p & 0xFFFFF;
        int et  = p >> 20;
        const float2* row = (const float2*)(g_t + ((size_t)et * NN + src) * 64);
        float2 v = row[lane];
        acc.x += v.x;
        acc.y += v.y;
    }
    if (relu) { acc.x = fmaxf(acc.x, 0.f); acc.y = fmaxf(acc.y, 0.f); }
    *(float2*)(out + (size_t)warp * 64 + lane * 2) = acc;
}

// ---------------- graph mean + attributor MLP ----------------
__global__ void mean_kernel(const float* __restrict__ h2) {
    int dim  = threadIdx.x & 63;
    int rgrp = threadIdx.x >> 6;  // 0..3
    float acc = 0.f;
    for (int row = blockIdx.x * 4 + rgrp; row < NN; row += gridDim.x * 4)
        acc += h2[(size_t)row * 64 + dim];
    __shared__ float s[256];
    s[threadIdx.x] = acc;
    __syncthreads();
    if (threadIdx.x < 64) {
        float v = s[threadIdx.x] + s[threadIdx.x + 64] + s[threadIdx.x + 128] + s[threadIdx.x + 192];
        atomicAdd(&g_gsum[threadIdx.x], v);
    }
}

__global__ void mlp_kernel(const float* __restrict__ A1w, const float* __restrict__ A1b,
                           const float* __restrict__ A2w, const float* __restrict__ A2b,
                           float* __restrict__ out) {
    __shared__ float g[64];
    __shared__ float hid[32];
    int tid = threadIdx.x;
    if (tid < 64) g[tid] = g_gsum[tid] * (1.0f / (float)NN);
    __syncthreads();
    if (tid < 32) {
        float s = A1b[tid];
        #pragma unroll
        for (int k = 0; k < 64; k++) s += g[k] * A1w[k * 32 + tid];
        hid[tid] = fmaxf(s, 0.f);
    }
    __syncthreads();
    if (tid < 10) {
        float s = A2b[tid];
        #pragma unroll
        for (int k = 0; k < 32; k++) s += hid[k] * A2w[k * 10 + tid];
        out[(size_t)NN * 64 + tid] = 1.0f / (1.0f + expf(-s));
    }
}

// ---------------- launch ----------------
extern "C" void kernel_launch(void* const* d_in, const int* in_sizes, int n_in,
                              void* d_out, int out_size) {
    const float* h   = (const float*)d_in[0];
    const int*   src = (const int*)d_in[1];
    const int*   dst = (const int*)d_in[2];
    const int*   et  = (const int*)d_in[3];
    const float* W1  = (const float*)d_in[4];
    const float* W2  = (const float*)d_in[5];
    const float* A1w = (const float*)d_in[6];
    const float* A1b = (const float*)d_in[7];
    const float* A2w = (const float*)d_in[8];
    const float* A2b = (const float*)d_in[9];
    float* out = (float*)d_out;

    void* h1_ptr = nullptr;
    cudaGetSymbolAddress(&h1_ptr, g_h1);
    float* h1 = (float*)h1_ptr;

    const int TB = 256;
    const int edge_blocks = (EE + TB - 1) / TB;   // grid-stride anyway
    const int node_blocks = (NN + TB - 1) / TB;

    // build dst-sorted edge list (counting sort)
    zero_kernel<<<node_blocks, TB>>>();
    count_kernel<<<edge_blocks, TB>>>(dst);
    scan_kernel<<<1, 1024>>>();
    init_cursor_kernel<<<node_blocks, TB>>>();
    scatter_kernel<<<edge_blocks, TB>>>(src, dst, et);

    dim3 ggrid((NN + 63) / 64, RR);
    const int agg_blocks = (NN * 32 + TB - 1) / TB;  // one warp per node

    // layer 1: t = h @ W1[r]; h1 = relu(segment_sum)
    gemm_kernel<<<ggrid, 128>>>(h, W1);
    agg_kernel<<<agg_blocks, TB>>>(h1, 1);

    // layer 2: t = h1 @ W2[r]; h2 = segment_sum -> d_out
    gemm_kernel<<<ggrid, 128>>>(h1, W2);
    agg_kernel<<<agg_blocks, TB>>>(out, 0);

    // graph mean + MLP -> d_out tail
    mean_kernel<<<512, 256>>>(out);
    mlp_kernel<<<1, 64>>>(A1w, A1b, A2w, A2b, out);
}